// round 13
// baseline (speedup 1.0000x reference)
#include <cuda_runtime.h>
#include <cuda_fp16.h>
#include <cstdint>

#define NN 100000
#define NE 1600000
#define DF 256
#define HID 256
#define NC 64

// ===================== helpers ==============================================
__device__ __forceinline__ uint32_t smem_to_u32(const void* p) {
    uint32_t a;
    asm("{ .reg .u64 t; cvta.to.shared.u64 t, %1; cvt.u32.u64 %0, t; }" : "=r"(a) : "l"(p));
    return a;
}
__device__ __forceinline__ void ldsm4(uint32_t* r, uint32_t addr) {
    asm volatile("ldmatrix.sync.aligned.m8n8.x4.shared.b16 {%0,%1,%2,%3}, [%4];"
                 : "=r"(r[0]), "=r"(r[1]), "=r"(r[2]), "=r"(r[3]) : "r"(addr));
}
__device__ __forceinline__ void mma_f16(float* d, const uint32_t* a, uint32_t b0, uint32_t b1) {
    asm volatile("mma.sync.aligned.m16n8k16.row.col.f32.f16.f16.f32 "
                 "{%0,%1,%2,%3}, {%4,%5,%6,%7}, {%8,%9}, {%0,%1,%2,%3};"
                 : "+f"(d[0]), "+f"(d[1]), "+f"(d[2]), "+f"(d[3])
                 : "r"(a[0]), "r"(a[1]), "r"(a[2]), "r"(a[3]), "r"(b0), "r"(b1));
}
__device__ __forceinline__ uint32_t pack_h2(float x, float y) {
    __half2 h = __floats2half2_rn(x, y);
    return *reinterpret_cast<uint32_t*>(&h);
}
__device__ __forceinline__ void add8s(float* acc, uint4 v, float s) {
    const __half2* hp = reinterpret_cast<const __half2*>(&v);
#pragma unroll
    for (int j = 0; j < 4; j++) {
        float2 f = __half22float2(hp[j]);
        acc[2 * j]     += s * f.x;
        acc[2 * j + 1] += s * f.y;
    }
}
__device__ __forceinline__ void add8(float* acc, uint4 v) {
    const __half2* hp = reinterpret_cast<const __half2*>(&v);
#pragma unroll
    for (int j = 0; j < 4; j++) {
        float2 f = __half22float2(hp[j]);
        acc[2 * j]     += f.x;
        acc[2 * j + 1] += f.y;
    }
}

// ===================== scratch (device globals) ==============================
__device__ __half g_w1t[HID * DF];
__device__ __half g_w2th[NC * HID];
__device__ __half g_w2tl[NC * HID];
__device__ __align__(16) __half g_h1[(size_t)NN * HID];
__device__ __align__(16) __half g_a1[(size_t)NN * HID];
__device__ __align__(16) __half g_h2[(size_t)NN * NC];   // dinv-scaled (GEMM2 epi)
__device__ int   g_deg[NN];
__device__ float g_dinv[NN];
__device__ int   g_offs[NN + 1];
__device__ int   g_cursor[NN];
__device__ int   g_csr[NE];
__device__ int   g_blocksums[128];

// ===================== prep: transposed weights ==============================
__global__ void k_prep_w1(const float* __restrict__ W) {
    int i = blockIdx.x * blockDim.x + threadIdx.x;
    if (i < DF * HID) {
        int k = i / HID, n = i % HID;
        g_w1t[n * DF + k] = __float2half_rn(W[(size_t)k * HID + n]);
    }
}
__global__ void k_prep_w2(const float* __restrict__ W) {
    int i = blockIdx.x * blockDim.x + threadIdx.x;
    if (i < HID * NC) {
        int k = i / NC, n = i % NC;
        float v = W[(size_t)k * NC + n];
        __half h = __float2half_rn(v);
        g_w2th[n * HID + k] = h;
        g_w2tl[n * HID + k] = __float2half_rn(v - __half2float(h));
    }
}

// ===================== CSR build =============================================
__global__ void k_init() {
    int i = blockIdx.x * blockDim.x + threadIdx.x;
    if (i < NN) { g_deg[i] = 1; g_cursor[i] = 0; }
}
__global__ void k_count(const int* __restrict__ ei) {
    int e4 = blockIdx.x * blockDim.x + threadIdx.x;
    if (e4 < NE / 4) {
        int4 c = ((const int4*)(ei + NE))[e4];
        if ((unsigned)c.x < NN) atomicAdd(&g_deg[c.x], 1);
        if ((unsigned)c.y < NN) atomicAdd(&g_deg[c.y], 1);
        if ((unsigned)c.z < NN) atomicAdd(&g_deg[c.z], 1);
        if ((unsigned)c.w < NN) atomicAdd(&g_deg[c.w], 1);
    }
}
__global__ void k_scan1() {   // also emits dinv
    __shared__ int s[1024];
    int tid = threadIdx.x;
    int gid = blockIdx.x * 1024 + tid;
    int v = (gid < NN) ? (g_deg[gid] - 1) : 0;
    if (gid < NN) g_dinv[gid] = rsqrtf((float)(v + 1));
    s[tid] = v;
    __syncthreads();
#pragma unroll
    for (int d = 1; d < 1024; d <<= 1) {
        int t = (tid >= d) ? s[tid - d] : 0;
        __syncthreads();
        s[tid] += t;
        __syncthreads();
    }
    if (gid < NN) g_offs[gid + 1] = s[tid];
    if (tid == 1023) g_blocksums[blockIdx.x] = s[1023];
    if (gid == 0) g_offs[0] = 0;
}
__global__ void k_scan2(int nb) {
    __shared__ int s[128];
    int tid = threadIdx.x;
    int v = (tid < nb) ? g_blocksums[tid] : 0;
    s[tid] = v;
    __syncthreads();
#pragma unroll
    for (int d = 1; d < 128; d <<= 1) {
        int t = (tid >= d) ? s[tid - d] : 0;
        __syncthreads();
        s[tid] += t;
        __syncthreads();
    }
    if (tid < nb) g_blocksums[tid] = s[tid] - v;
}
__global__ void k_scan3() {
    int gid = blockIdx.x * 1024 + threadIdx.x;
    if (gid < NN) g_offs[gid + 1] += g_blocksums[blockIdx.x];
}
__global__ void k_scatter(const int* __restrict__ ei) {
    int e4 = blockIdx.x * blockDim.x + threadIdx.x;
    if (e4 < NE / 4) {
        int4 r = ((const int4*)ei)[e4];
        int4 c = ((const int4*)(ei + NE))[e4];
        if ((unsigned)r.x < NN && (unsigned)c.x < NN)
            g_csr[g_offs[c.x] + atomicAdd(&g_cursor[c.x], 1)] = r.x;
        if ((unsigned)r.y < NN && (unsigned)c.y < NN)
            g_csr[g_offs[c.y] + atomicAdd(&g_cursor[c.y], 1)] = r.y;
        if ((unsigned)r.z < NN && (unsigned)c.z < NN)
            g_csr[g_offs[c.z] + atomicAdd(&g_cursor[c.z], 1)] = r.z;
        if ((unsigned)r.w < NN && (unsigned)c.w < NN)
            g_csr[g_offs[c.w] + atomicAdd(&g_cursor[c.w], 1)] = r.w;
    }
}

// ===================== fp16 HMMA GEMM, 2-stage SMEM pipeline =================
// LAYER 1: C = round16(A_fp32) @ W1(fp16), UNscaled.
// LAYER 2: C = dinv[m] * (A(fp16) @ W2(hi/lo)) — dinv folded in epilogue.
template <int BN, int NT, int LAYER, int THREADS, int WNG, int MINCTA>
__global__ void __launch_bounds__(THREADS, MINCTA) k_gemm_mma(const float* __restrict__ A_ext) {
    constexpr int WTN = BN / WNG;
    constexpr int NTL = WTN / 8;
    constexpr int KDIM = 256;
    constexpr int NCH = KDIM / 32;
    constexpr int ASL = (128 * 4) / THREADS;
    constexpr int BSL = (BN * 4) / THREADS;
    constexpr int A_BYTES = 128 * 80;
    constexpr int B_OFF   = A_BYTES;
    constexpr int B1_OFF  = A_BYTES + BN * 80;
    constexpr int STAGE   = A_BYTES + BN * 80 * ((LAYER == 2) ? 2 : 1);

    extern __shared__ __align__(16) char smem_dyn[];
    const uint32_t smem_b = smem_to_u32(smem_dyn);

    __half* __restrict__ C = (LAYER == 1) ? g_h1 : g_h2;

    const int tid = threadIdx.x, wid = tid >> 5, lane = tid & 31;
    const int bm = blockIdx.x * 128;
    const int m_off = (wid / WNG) * 32;
    const int n_off = (wid % WNG) * WTN;

    float4 pA[ASL][2];
    uint4 pA16[ASL];
    uint4 pB0[BSL], pB1[BSL];

    auto ld_chunk = [&](int c) {
        const int k0 = c * 32;
#pragma unroll
        for (int sl = 0; sl < ASL; sl++) {
            int idx = tid + sl * THREADS;
            int r = idx >> 2, seg = idx & 3;
            int gr = bm + r;
            if (LAYER == 1) {
                if (gr < NN) {
                    const float4* p4 = (const float4*)(A_ext + (size_t)gr * KDIM + k0 + seg * 8);
                    pA[sl][0] = p4[0]; pA[sl][1] = p4[1];
                } else { pA[sl][0] = make_float4(0, 0, 0, 0); pA[sl][1] = pA[sl][0]; }
            } else {
                if (gr < NN)
                    pA16[sl] = *(const uint4*)(g_a1 + (size_t)gr * KDIM + k0 + seg * 8);
                else
                    pA16[sl] = make_uint4(0, 0, 0, 0);
            }
        }
#pragma unroll
        for (int sl = 0; sl < BSL; sl++) {
            int it = tid + sl * THREADS;
            int n = it >> 2, seg = it & 3;
            size_t off = ((size_t)n * KDIM + k0) * 2 + seg * 16;
            if (LAYER == 1) {
                pB0[sl] = *(const uint4*)((const char*)g_w1t + off);
            } else {
                pB0[sl] = *(const uint4*)((const char*)g_w2th + off);
                pB1[sl] = *(const uint4*)((const char*)g_w2tl + off);
            }
        }
    };
    auto st_chunk = [&](int stage) {
        char* sbase = smem_dyn + stage * STAGE;
#pragma unroll
        for (int sl = 0; sl < ASL; sl++) {
            int idx = tid + sl * THREADS;
            int r = idx >> 2, seg = idx & 3;
            if (LAYER == 1) {
                uint4 h4;
                h4.x = pack_h2(pA[sl][0].x, pA[sl][0].y);
                h4.y = pack_h2(pA[sl][0].z, pA[sl][0].w);
                h4.z = pack_h2(pA[sl][1].x, pA[sl][1].y);
                h4.w = pack_h2(pA[sl][1].z, pA[sl][1].w);
                *(uint4*)(sbase + r * 80 + seg * 16) = h4;
            } else {
                *(uint4*)(sbase + r * 80 + seg * 16) = pA16[sl];
            }
        }
#pragma unroll
        for (int sl = 0; sl < BSL; sl++) {
            int it = tid + sl * THREADS;
            int n = it >> 2, seg = it & 3;
            *(uint4*)(sbase + B_OFF + n * 80 + seg * 16) = pB0[sl];
            if (LAYER == 2)
                *(uint4*)(sbase + B1_OFF + n * 80 + seg * 16) = pB1[sl];
        }
    };

    float acc[2][NTL][4];
#pragma unroll
    for (int t = 0; t < 2; t++)
#pragma unroll
        for (int p = 0; p < NTL; p++)
#pragma unroll
            for (int j = 0; j < 4; j++) acc[t][p][j] = 0.f;

    ld_chunk(0);
    st_chunk(0);
    __syncthreads();

    for (int c = 0; c < NCH; c++) {
        const int stg = c & 1;
        if (c + 1 < NCH) ld_chunk(c + 1);

        const uint32_t a_st = smem_b + stg * STAGE;
        const uint32_t b0_st = a_st + B_OFF;
        const uint32_t b1_st = a_st + B1_OFF;

#pragma unroll
        for (int s = 0; s < 2; s++) {
            const int kb = s * 32;
            uint32_t a0[2][4];
#pragma unroll
            for (int t = 0; t < 2; t++) {
                uint32_t ra = (uint32_t)(m_off + t * 16 + (lane & 15)) * 80 + kb + (lane >> 4) * 16;
                ldsm4(a0[t], a_st + ra);
            }
#pragma unroll
            for (int p = 0; p < NTL / 2; p++) {
                uint32_t rb = (uint32_t)(n_off + p * 16 + (lane >> 4) * 8 + (lane & 7)) * 80 +
                              kb + ((lane >> 3) & 1) * 16;
                uint32_t b0[4];
                ldsm4(b0, b0_st + rb);
#pragma unroll
                for (int t = 0; t < 2; t++) {
                    mma_f16(acc[t][2 * p],     a0[t], b0[0], b0[1]);
                    mma_f16(acc[t][2 * p + 1], a0[t], b0[2], b0[3]);
                }
                if (LAYER == 2) {
                    uint32_t b1[4];
                    ldsm4(b1, b1_st + rb);
#pragma unroll
                    for (int t = 0; t < 2; t++) {
                        mma_f16(acc[t][2 * p],     a0[t], b1[0], b1[1]);
                        mma_f16(acc[t][2 * p + 1], a0[t], b1[2], b1[3]);
                    }
                }
            }
        }

        if (c + 1 < NCH) {
            st_chunk((c + 1) & 1);
            __syncthreads();
        }
    }

#pragma unroll
    for (int t = 0; t < 2; t++) {
        int m0 = bm + m_off + t * 16 + (lane >> 2);
        int m1 = m0 + 8;
        float s0 = 1.f, s1 = 1.f;
        if (LAYER == 2) {
            s0 = (m0 < NN) ? g_dinv[m0] : 0.f;
            s1 = (m1 < NN) ? g_dinv[m1] : 0.f;
        }
#pragma unroll
        for (int p = 0; p < NTL; p++) {
            int n = n_off + p * 8 + (lane & 3) * 2;
            if (m0 < NN)
                *(__half2*)(C + (size_t)m0 * NT + n) =
                    __floats2half2_rn(s0 * acc[t][p][0], s0 * acc[t][p][1]);
            if (m1 < NN)
                *(__half2*)(C + (size_t)m1 * NT + n) =
                    __floats2half2_rn(s1 * acc[t][p][2], s1 * acc[t][p][3]);
        }
    }
}

// ===================== aggregation ===========================================
// Layer 1: h1 UNscaled; per-edge dinv applied here. 4 nodes per warp (balance).
template <bool RELU>
__global__ void __launch_bounds__(256) k_agg1_f16(const float* __restrict__ bias) {
    const uint4* __restrict__ hv = (const uint4*)g_h1;
    uint4* __restrict__ ov = (uint4*)g_a1;

    const int tid = threadIdx.x, wid = tid >> 5, lane = tid & 31;
    const int wglobal = blockIdx.x * 8 + wid;

    float4 b0 = ((const float4*)bias)[lane * 2];
    float4 b1 = ((const float4*)bias)[lane * 2 + 1];

    for (int i = 0; i < 4; i++) {
        const int node = wglobal * 4 + i;   // NN = 100000 = 3125*32, exact
        const int s = g_offs[node], e = g_offs[node + 1];
        const float dv = g_dinv[node];

        float acc[8];
        {
            uint4 v = hv[(size_t)node * 32 + lane];
            const __half2* hp = reinterpret_cast<const __half2*>(&v);
#pragma unroll
            for (int j = 0; j < 4; j++) {
                float2 f = __half22float2(hp[j]);
                acc[2 * j] = dv * f.x; acc[2 * j + 1] = dv * f.y;
            }
        }

        int base = s;
        while (base < e) {
            int n = e - base;
            if (n > 32) n = 32;
            int idx = g_csr[base + min(lane, n - 1)];
            int j = 0;
            for (; j + 8 <= n; j += 8) {
                int r[8]; float d[8]; uint4 t[8];
#pragma unroll
                for (int q = 0; q < 8; q++) r[q] = __shfl_sync(0xFFFFFFFFu, idx, j + q);
#pragma unroll
                for (int q = 0; q < 8; q++) d[q] = g_dinv[r[q]];
#pragma unroll
                for (int q = 0; q < 8; q++) t[q] = hv[(size_t)r[q] * 32 + lane];
#pragma unroll
                for (int q = 0; q < 8; q++) add8s(acc, t[q], d[q]);
            }
            for (; j < n; j++) {
                int r = __shfl_sync(0xFFFFFFFFu, idx, j);
                add8s(acc, hv[(size_t)r * 32 + lane], g_dinv[r]);
            }
            base += n;
        }

        float o[8];
        o[0] = dv * acc[0] + b0.x; o[1] = dv * acc[1] + b0.y;
        o[2] = dv * acc[2] + b0.z; o[3] = dv * acc[3] + b0.w;
        o[4] = dv * acc[4] + b1.x; o[5] = dv * acc[5] + b1.y;
        o[6] = dv * acc[6] + b1.z; o[7] = dv * acc[7] + b1.w;
        if (RELU) {
#pragma unroll
            for (int j = 0; j < 8; j++) o[j] = fmaxf(o[j], 0.f);
        }
        uint4 pk;
        __half2* op = reinterpret_cast<__half2*>(&pk);
#pragma unroll
        for (int j = 0; j < 4; j++) op[j] = __floats2half2_rn(o[2 * j], o[2 * j + 1]);
        ov[(size_t)node * 32 + lane] = pk;
    }
}

// Layer 2: h2 is PRE-scaled by dinv[m] (GEMM2 epilogue) -> plain adds.
// 8 threads/node, 4 nodes per group.
__global__ void __launch_bounds__(256) k_agg2_f16(const float* __restrict__ bias,
                                                  float* __restrict__ outp) {
    const uint4* __restrict__ hv = (const uint4*)g_h2;

    const int tid = threadIdx.x;
    const int sub = tid & 7;
    const int group = blockIdx.x * 32 + (tid >> 3);
    const int lane = tid & 31;
    const unsigned gmask = 0xFFu << (lane & ~7);

    float4 b0 = ((const float4*)bias)[sub * 2];
    float4 b1 = ((const float4*)bias)[sub * 2 + 1];

    for (int i = 0; i < 4; i++) {
        const int node = group * 4 + i;
        if (node >= NN) return;
        const int s = g_offs[node], e = g_offs[node + 1];
        const float dv = g_dinv[node];

        float acc[8];
        {
            uint4 v = hv[(size_t)node * 8 + sub];   // already dinv[v]-scaled
            const __half2* hp = reinterpret_cast<const __half2*>(&v);
#pragma unroll
            for (int j = 0; j < 4; j++) {
                float2 f = __half22float2(hp[j]);
                acc[2 * j] = f.x; acc[2 * j + 1] = f.y;
            }
        }

        int base = s;
        while (base < e) {
            int n = e - base;
            if (n > 8) n = 8;
            int idx = g_csr[base + min(sub, n - 1)];
            int j = 0;
            for (; j + 8 <= n; j += 8) {
                int r[8]; uint4 t[8];
#pragma unroll
                for (int q = 0; q < 8; q++) r[q] = __shfl_sync(gmask, idx, j + q, 8);
#pragma unroll
                for (int q = 0; q < 8; q++) t[q] = hv[(size_t)r[q] * 8 + sub];
#pragma unroll
                for (int q = 0; q < 8; q++) add8(acc, t[q]);
            }
            for (; j < n; j++) {
                int r = __shfl_sync(gmask, idx, j, 8);
                add8(acc, hv[(size_t)r * 8 + sub]);
            }
            base += n;
        }

        float4 v0, v1;
        v0.x = dv * acc[0] + b0.x; v0.y = dv * acc[1] + b0.y;
        v0.z = dv * acc[2] + b0.z; v0.w = dv * acc[3] + b0.w;
        v1.x = dv * acc[4] + b1.x; v1.y = dv * acc[5] + b1.y;
        v1.z = dv * acc[6] + b1.z; v1.w = dv * acc[7] + b1.w;
        float4* op = (float4*)(outp + (size_t)node * NC + sub * 8);
        op[0] = v0; op[1] = v1;
    }
}

// ===================== side stream (static init; no device allocation) =======
struct SideStream {
    cudaStream_t s = nullptr;
    cudaEvent_t evF = nullptr, evJ = nullptr;
    SideStream() {
        if (cudaStreamCreateWithFlags(&s, cudaStreamNonBlocking) != cudaSuccess) s = nullptr;
        if (cudaEventCreateWithFlags(&evF, cudaEventDisableTiming) != cudaSuccess) evF = nullptr;
        if (cudaEventCreateWithFlags(&evJ, cudaEventDisableTiming) != cudaSuccess) evJ = nullptr;
    }
};
static SideStream g_ss;

// ===================== launch =================================================
extern "C" void kernel_launch(void* const* d_in, const int* in_sizes, int n_in,
                              void* d_out, int out_size) {
    const float* x  = (const float*)d_in[0];
    const int*   ei = (const int*)d_in[1];
    const float* W1 = (const float*)d_in[2];
    const float* b1 = (const float*)d_in[3];
    const float* W2 = (const float*)d_in[4];
    const float* b2 = (const float*)d_in[5];
    float* out = (float*)d_out;

    const int NB_SCAN = (NN + 1023) / 1024;  // 98
    const int NTILES  = (NN + 127) / 128;    // 782
    const int NB_E4   = (NE / 4 + 255) / 256;

    constexpr int SMEM1 = 2 * (128 * 80 + 256 * 80);     // 61440
    constexpr int SMEM2 = 2 * (128 * 80 + 2 * 64 * 80);  // 40960
    cudaFuncSetAttribute(k_gemm_mma<256, HID, 1, 512, 4, 1>,
                         cudaFuncAttributeMaxDynamicSharedMemorySize, SMEM1);
    cudaFuncSetAttribute(k_gemm_mma<64, NC, 2, 256, 2, 2>,
                         cudaFuncAttributeMaxDynamicSharedMemorySize, SMEM2);

    // ---- fork: CSR branch on side stream, GEMM1 branch on main stream ----
    bool fork = (g_ss.s && g_ss.evF && g_ss.evJ);
    if (fork) fork = (cudaEventRecord(g_ss.evF, 0) == cudaSuccess);
    if (fork) fork = (cudaStreamWaitEvent(g_ss.s, g_ss.evF, 0) == cudaSuccess);
    cudaStream_t cs = fork ? g_ss.s : (cudaStream_t)0;

    // CSR branch (independent of x/W1)
    k_init<<<(NN + 255) / 256, 256, 0, cs>>>();
    k_count<<<NB_E4, 256, 0, cs>>>(ei);
    k_scan1<<<NB_SCAN, 1024, 0, cs>>>();
    k_scan2<<<1, 128, 0, cs>>>(NB_SCAN);
    k_scan3<<<NB_SCAN, 1024, 0, cs>>>();
    k_scatter<<<NB_E4, 256, 0, cs>>>(ei);
    k_prep_w2<<<(HID * NC + 255) / 256, 256, 0, cs>>>(W2);

    // GEMM branch (independent of edges)
    k_prep_w1<<<(DF * HID + 255) / 256, 256>>>(W1);
    k_gemm_mma<256, HID, 1, 512, 4, 1><<<NTILES, 512, SMEM1>>>(x);

    // ---- join ----
    if (fork) {
        bool ok = (cudaEventRecord(g_ss.evJ, g_ss.s) == cudaSuccess);
        if (ok) ok = (cudaStreamWaitEvent(0, g_ss.evJ, 0) == cudaSuccess);
        (void)ok;
    }

    // fused remainder (needs both branches)
    k_agg1_f16<true><<<NN / 32, 256>>>(b1);
    k_gemm_mma<64, NC, 2, 256, 2, 2><<<NTILES, 256, SMEM2>>>(nullptr);
    k_agg2_f16<<<(NN + 127) / 128, 256>>>(b2, out);
}

// round 14
// speedup vs baseline: 1.0203x; 1.0203x over previous
#include <cuda_runtime.h>
#include <cuda_fp16.h>
#include <cstdint>

#define NN 100000
#define NE 1600000
#define DF 256
#define HID 256
#define NC 64

// ===================== helpers ==============================================
__device__ __forceinline__ uint32_t smem_to_u32(const void* p) {
    uint32_t a;
    asm("{ .reg .u64 t; cvta.to.shared.u64 t, %1; cvt.u32.u64 %0, t; }" : "=r"(a) : "l"(p));
    return a;
}
__device__ __forceinline__ void ldsm4(uint32_t* r, uint32_t addr) {
    asm volatile("ldmatrix.sync.aligned.m8n8.x4.shared.b16 {%0,%1,%2,%3}, [%4];"
                 : "=r"(r[0]), "=r"(r[1]), "=r"(r[2]), "=r"(r[3]) : "r"(addr));
}
__device__ __forceinline__ void mma_f16(float* d, const uint32_t* a, uint32_t b0, uint32_t b1) {
    asm volatile("mma.sync.aligned.m16n8k16.row.col.f32.f16.f16.f32 "
                 "{%0,%1,%2,%3}, {%4,%5,%6,%7}, {%8,%9}, {%0,%1,%2,%3};"
                 : "+f"(d[0]), "+f"(d[1]), "+f"(d[2]), "+f"(d[3])
                 : "r"(a[0]), "r"(a[1]), "r"(a[2]), "r"(a[3]), "r"(b0), "r"(b1));
}
__device__ __forceinline__ uint32_t pack_h2(float x, float y) {
    __half2 h = __floats2half2_rn(x, y);
    return *reinterpret_cast<uint32_t*>(&h);
}
__device__ __forceinline__ void add8s(float* acc, uint4 v, float s) {
    const __half2* hp = reinterpret_cast<const __half2*>(&v);
#pragma unroll
    for (int j = 0; j < 4; j++) {
        float2 f = __half22float2(hp[j]);
        acc[2 * j]     += s * f.x;
        acc[2 * j + 1] += s * f.y;
    }
}
__device__ __forceinline__ void add8(float* acc, uint4 v) {
    const __half2* hp = reinterpret_cast<const __half2*>(&v);
#pragma unroll
    for (int j = 0; j < 4; j++) {
        float2 f = __half22float2(hp[j]);
        acc[2 * j]     += f.x;
        acc[2 * j + 1] += f.y;
    }
}

// ===================== scratch (device globals) ==============================
__device__ __half g_w1t[HID * DF];
__device__ __half g_w2th[NC * HID];
__device__ __half g_w2tl[NC * HID];
__device__ __align__(16) __half g_h1[(size_t)NN * HID];
__device__ __align__(16) __half g_a1[(size_t)NN * HID];
__device__ __align__(16) __half g_h2[(size_t)NN * NC];   // dinv-scaled (GEMM2 epi)
__device__ int   g_deg[NN];
__device__ float g_dinv[NN];
__device__ int   g_offs[NN + 1];
__device__ int   g_cursor[NN];
__device__ int   g_csr[NE];
__device__ int   g_blocksums[128];

// ===================== prep: transposed weights ==============================
__global__ void k_prep_w1(const float* __restrict__ W) {
    int i = blockIdx.x * blockDim.x + threadIdx.x;
    if (i < DF * HID) {
        int k = i / HID, n = i % HID;
        g_w1t[n * DF + k] = __float2half_rn(W[(size_t)k * HID + n]);
    }
}
__global__ void k_prep_w2(const float* __restrict__ W) {
    int i = blockIdx.x * blockDim.x + threadIdx.x;
    if (i < HID * NC) {
        int k = i / NC, n = i % NC;
        float v = W[(size_t)k * NC + n];
        __half h = __float2half_rn(v);
        g_w2th[n * HID + k] = h;
        g_w2tl[n * HID + k] = __float2half_rn(v - __half2float(h));
    }
}

// ===================== CSR build =============================================
__global__ void k_init() {
    int i = blockIdx.x * blockDim.x + threadIdx.x;
    if (i < NN) { g_deg[i] = 1; g_cursor[i] = 0; }
}
__global__ void k_count(const int* __restrict__ ei) {
    int e4 = blockIdx.x * blockDim.x + threadIdx.x;
    if (e4 < NE / 4) {
        int4 c = ((const int4*)(ei + NE))[e4];
        if ((unsigned)c.x < NN) atomicAdd(&g_deg[c.x], 1);
        if ((unsigned)c.y < NN) atomicAdd(&g_deg[c.y], 1);
        if ((unsigned)c.z < NN) atomicAdd(&g_deg[c.z], 1);
        if ((unsigned)c.w < NN) atomicAdd(&g_deg[c.w], 1);
    }
}
__global__ void k_scan1() {   // also emits dinv
    __shared__ int s[1024];
    int tid = threadIdx.x;
    int gid = blockIdx.x * 1024 + tid;
    int v = (gid < NN) ? (g_deg[gid] - 1) : 0;
    if (gid < NN) g_dinv[gid] = rsqrtf((float)(v + 1));
    s[tid] = v;
    __syncthreads();
#pragma unroll
    for (int d = 1; d < 1024; d <<= 1) {
        int t = (tid >= d) ? s[tid - d] : 0;
        __syncthreads();
        s[tid] += t;
        __syncthreads();
    }
    if (gid < NN) g_offs[gid + 1] = s[tid];
    if (tid == 1023) g_blocksums[blockIdx.x] = s[1023];
    if (gid == 0) g_offs[0] = 0;
}
__global__ void k_scan2(int nb) {
    __shared__ int s[128];
    int tid = threadIdx.x;
    int v = (tid < nb) ? g_blocksums[tid] : 0;
    s[tid] = v;
    __syncthreads();
#pragma unroll
    for (int d = 1; d < 128; d <<= 1) {
        int t = (tid >= d) ? s[tid - d] : 0;
        __syncthreads();
        s[tid] += t;
        __syncthreads();
    }
    if (tid < nb) g_blocksums[tid] = s[tid] - v;
}
__global__ void k_scan3() {
    int gid = blockIdx.x * 1024 + threadIdx.x;
    if (gid < NN) g_offs[gid + 1] += g_blocksums[blockIdx.x];
}
__global__ void k_scatter(const int* __restrict__ ei) {
    int e4 = blockIdx.x * blockDim.x + threadIdx.x;
    if (e4 < NE / 4) {
        int4 r = ((const int4*)ei)[e4];
        int4 c = ((const int4*)(ei + NE))[e4];
        if ((unsigned)r.x < NN && (unsigned)c.x < NN)
            g_csr[g_offs[c.x] + atomicAdd(&g_cursor[c.x], 1)] = r.x;
        if ((unsigned)r.y < NN && (unsigned)c.y < NN)
            g_csr[g_offs[c.y] + atomicAdd(&g_cursor[c.y], 1)] = r.y;
        if ((unsigned)r.z < NN && (unsigned)c.z < NN)
            g_csr[g_offs[c.z] + atomicAdd(&g_cursor[c.z], 1)] = r.z;
        if ((unsigned)r.w < NN && (unsigned)c.w < NN)
            g_csr[g_offs[c.w] + atomicAdd(&g_cursor[c.w], 1)] = r.w;
    }
}

// ===================== fp16 HMMA GEMM, 2-stage SMEM pipeline =================
// LAYER 1: C = round16(A_fp32) @ W1(fp16), UNscaled.
// LAYER 2: C = dinv[m] * (A(fp16) @ W2(hi/lo)) — dinv folded in epilogue.
// tile_off: M-tile offset (for chunked launches).
template <int BN, int NT, int LAYER, int THREADS, int WNG, int MINCTA>
__global__ void __launch_bounds__(THREADS, MINCTA) k_gemm_mma(const float* __restrict__ A_ext,
                                                              int tile_off) {
    constexpr int WTN = BN / WNG;
    constexpr int NTL = WTN / 8;
    constexpr int KDIM = 256;
    constexpr int NCH = KDIM / 32;
    constexpr int ASL = (128 * 4) / THREADS;
    constexpr int BSL = (BN * 4) / THREADS;
    constexpr int A_BYTES = 128 * 80;
    constexpr int B_OFF   = A_BYTES;
    constexpr int B1_OFF  = A_BYTES + BN * 80;
    constexpr int STAGE   = A_BYTES + BN * 80 * ((LAYER == 2) ? 2 : 1);

    extern __shared__ __align__(16) char smem_dyn[];
    const uint32_t smem_b = smem_to_u32(smem_dyn);

    __half* __restrict__ C = (LAYER == 1) ? g_h1 : g_h2;

    const int tid = threadIdx.x, wid = tid >> 5, lane = tid & 31;
    const int bm = (blockIdx.x + tile_off) * 128;
    const int m_off = (wid / WNG) * 32;
    const int n_off = (wid % WNG) * WTN;

    float4 pA[ASL][2];
    uint4 pA16[ASL];
    uint4 pB0[BSL], pB1[BSL];

    auto ld_chunk = [&](int c) {
        const int k0 = c * 32;
#pragma unroll
        for (int sl = 0; sl < ASL; sl++) {
            int idx = tid + sl * THREADS;
            int r = idx >> 2, seg = idx & 3;
            int gr = bm + r;
            if (LAYER == 1) {
                if (gr < NN) {
                    const float4* p4 = (const float4*)(A_ext + (size_t)gr * KDIM + k0 + seg * 8);
                    pA[sl][0] = p4[0]; pA[sl][1] = p4[1];
                } else { pA[sl][0] = make_float4(0, 0, 0, 0); pA[sl][1] = pA[sl][0]; }
            } else {
                if (gr < NN)
                    pA16[sl] = *(const uint4*)(g_a1 + (size_t)gr * KDIM + k0 + seg * 8);
                else
                    pA16[sl] = make_uint4(0, 0, 0, 0);
            }
        }
#pragma unroll
        for (int sl = 0; sl < BSL; sl++) {
            int it = tid + sl * THREADS;
            int n = it >> 2, seg = it & 3;
            size_t off = ((size_t)n * KDIM + k0) * 2 + seg * 16;
            if (LAYER == 1) {
                pB0[sl] = *(const uint4*)((const char*)g_w1t + off);
            } else {
                pB0[sl] = *(const uint4*)((const char*)g_w2th + off);
                pB1[sl] = *(const uint4*)((const char*)g_w2tl + off);
            }
        }
    };
    auto st_chunk = [&](int stage) {
        char* sbase = smem_dyn + stage * STAGE;
#pragma unroll
        for (int sl = 0; sl < ASL; sl++) {
            int idx = tid + sl * THREADS;
            int r = idx >> 2, seg = idx & 3;
            if (LAYER == 1) {
                uint4 h4;
                h4.x = pack_h2(pA[sl][0].x, pA[sl][0].y);
                h4.y = pack_h2(pA[sl][0].z, pA[sl][0].w);
                h4.z = pack_h2(pA[sl][1].x, pA[sl][1].y);
                h4.w = pack_h2(pA[sl][1].z, pA[sl][1].w);
                *(uint4*)(sbase + r * 80 + seg * 16) = h4;
            } else {
                *(uint4*)(sbase + r * 80 + seg * 16) = pA16[sl];
            }
        }
#pragma unroll
        for (int sl = 0; sl < BSL; sl++) {
            int it = tid + sl * THREADS;
            int n = it >> 2, seg = it & 3;
            *(uint4*)(sbase + B_OFF + n * 80 + seg * 16) = pB0[sl];
            if (LAYER == 2)
                *(uint4*)(sbase + B1_OFF + n * 80 + seg * 16) = pB1[sl];
        }
    };

    float acc[2][NTL][4];
#pragma unroll
    for (int t = 0; t < 2; t++)
#pragma unroll
        for (int p = 0; p < NTL; p++)
#pragma unroll
            for (int j = 0; j < 4; j++) acc[t][p][j] = 0.f;

    ld_chunk(0);
    st_chunk(0);
    __syncthreads();

    for (int c = 0; c < NCH; c++) {
        const int stg = c & 1;
        if (c + 1 < NCH) ld_chunk(c + 1);

        const uint32_t a_st = smem_b + stg * STAGE;
        const uint32_t b0_st = a_st + B_OFF;
        const uint32_t b1_st = a_st + B1_OFF;

#pragma unroll
        for (int s = 0; s < 2; s++) {
            const int kb = s * 32;
            uint32_t a0[2][4];
#pragma unroll
            for (int t = 0; t < 2; t++) {
                uint32_t ra = (uint32_t)(m_off + t * 16 + (lane & 15)) * 80 + kb + (lane >> 4) * 16;
                ldsm4(a0[t], a_st + ra);
            }
#pragma unroll
            for (int p = 0; p < NTL / 2; p++) {
                uint32_t rb = (uint32_t)(n_off + p * 16 + (lane >> 4) * 8 + (lane & 7)) * 80 +
                              kb + ((lane >> 3) & 1) * 16;
                uint32_t b0[4];
                ldsm4(b0, b0_st + rb);
#pragma unroll
                for (int t = 0; t < 2; t++) {
                    mma_f16(acc[t][2 * p],     a0[t], b0[0], b0[1]);
                    mma_f16(acc[t][2 * p + 1], a0[t], b0[2], b0[3]);
                }
                if (LAYER == 2) {
                    uint32_t b1[4];
                    ldsm4(b1, b1_st + rb);
#pragma unroll
                    for (int t = 0; t < 2; t++) {
                        mma_f16(acc[t][2 * p],     a0[t], b1[0], b1[1]);
                        mma_f16(acc[t][2 * p + 1], a0[t], b1[2], b1[3]);
                    }
                }
            }
        }

        if (c + 1 < NCH) {
            st_chunk((c + 1) & 1);
            __syncthreads();
        }
    }

#pragma unroll
    for (int t = 0; t < 2; t++) {
        int m0 = bm + m_off + t * 16 + (lane >> 2);
        int m1 = m0 + 8;
        float s0 = 1.f, s1 = 1.f;
        if (LAYER == 2) {
            s0 = (m0 < NN) ? g_dinv[m0] : 0.f;
            s1 = (m1 < NN) ? g_dinv[m1] : 0.f;
        }
#pragma unroll
        for (int p = 0; p < NTL; p++) {
            int n = n_off + p * 8 + (lane & 3) * 2;
            if (m0 < NN)
                *(__half2*)(C + (size_t)m0 * NT + n) =
                    __floats2half2_rn(s0 * acc[t][p][0], s0 * acc[t][p][1]);
            if (m1 < NN)
                *(__half2*)(C + (size_t)m1 * NT + n) =
                    __floats2half2_rn(s1 * acc[t][p][2], s1 * acc[t][p][3]);
        }
    }
}

// ===================== aggregation ===========================================
// Layer 1 (R12 form): one warp per node, 8 nodes per block; node_base for chunks.
template <bool RELU>
__global__ void __launch_bounds__(256) k_agg1_f16(const float* __restrict__ bias,
                                                  int node_base) {
    const uint4* __restrict__ hv = (const uint4*)g_h1;
    uint4* __restrict__ ov = (uint4*)g_a1;

    const int tid = threadIdx.x, wid = tid >> 5, lane = tid & 31;
    const int node = node_base + blockIdx.x * 8 + wid;
    if (node >= NN) return;
    const int s = g_offs[node], e = g_offs[node + 1];
    const float dv = g_dinv[node];

    float acc[8];
    {
        uint4 v = hv[(size_t)node * 32 + lane];
        const __half2* hp = reinterpret_cast<const __half2*>(&v);
#pragma unroll
        for (int j = 0; j < 4; j++) {
            float2 f = __half22float2(hp[j]);
            acc[2 * j] = dv * f.x; acc[2 * j + 1] = dv * f.y;
        }
    }

    int base = s;
    while (base < e) {
        int n = e - base;
        if (n > 32) n = 32;
        int idx = g_csr[base + min(lane, n - 1)];
        int j = 0;
        for (; j + 8 <= n; j += 8) {
            int r[8]; float d[8]; uint4 t[8];
#pragma unroll
            for (int q = 0; q < 8; q++) r[q] = __shfl_sync(0xFFFFFFFFu, idx, j + q);
#pragma unroll
            for (int q = 0; q < 8; q++) d[q] = g_dinv[r[q]];
#pragma unroll
            for (int q = 0; q < 8; q++) t[q] = hv[(size_t)r[q] * 32 + lane];
#pragma unroll
            for (int q = 0; q < 8; q++) add8s(acc, t[q], d[q]);
        }
        for (; j < n; j++) {
            int r = __shfl_sync(0xFFFFFFFFu, idx, j);
            add8s(acc, hv[(size_t)r * 32 + lane], g_dinv[r]);
        }
        base += n;
    }

    float4 b0 = ((const float4*)bias)[lane * 2];
    float4 b1 = ((const float4*)bias)[lane * 2 + 1];
    float o[8];
    o[0] = dv * acc[0] + b0.x; o[1] = dv * acc[1] + b0.y;
    o[2] = dv * acc[2] + b0.z; o[3] = dv * acc[3] + b0.w;
    o[4] = dv * acc[4] + b1.x; o[5] = dv * acc[5] + b1.y;
    o[6] = dv * acc[6] + b1.z; o[7] = dv * acc[7] + b1.w;
    if (RELU) {
#pragma unroll
        for (int j = 0; j < 8; j++) o[j] = fmaxf(o[j], 0.f);
    }
    uint4 pk;
    __half2* op = reinterpret_cast<__half2*>(&pk);
#pragma unroll
    for (int j = 0; j < 4; j++) op[j] = __floats2half2_rn(o[2 * j], o[2 * j + 1]);
    ov[(size_t)node * 32 + lane] = pk;
}

// Layer 2 (R12 layout): h2 PRE-scaled by dinv[m] -> plain adds. 8 thr/node.
__global__ void __launch_bounds__(256) k_agg2_f16(const float* __restrict__ bias,
                                                  float* __restrict__ outp) {
    const uint4* __restrict__ hv = (const uint4*)g_h2;

    const int tid = threadIdx.x;
    const int sub = tid & 7;
    const int node = blockIdx.x * 32 + (tid >> 3);
    const int lane = tid & 31;
    const unsigned gmask = 0xFFu << (lane & ~7);

    const int s = g_offs[node], e = g_offs[node + 1];
    const float dv = g_dinv[node];

    float acc[8];
    {
        uint4 v = hv[(size_t)node * 8 + sub];   // already dinv[v]-scaled
        const __half2* hp = reinterpret_cast<const __half2*>(&v);
#pragma unroll
        for (int j = 0; j < 4; j++) {
            float2 f = __half22float2(hp[j]);
            acc[2 * j] = f.x; acc[2 * j + 1] = f.y;
        }
    }

    int base = s;
    while (base < e) {
        int n = e - base;
        if (n > 8) n = 8;
        int idx = g_csr[base + min(sub, n - 1)];
        int j = 0;
        for (; j + 8 <= n; j += 8) {
            int r[8]; uint4 t[8];
#pragma unroll
            for (int q = 0; q < 8; q++) r[q] = __shfl_sync(gmask, idx, j + q, 8);
#pragma unroll
            for (int q = 0; q < 8; q++) t[q] = hv[(size_t)r[q] * 8 + sub];
#pragma unroll
            for (int q = 0; q < 8; q++) add8(acc, t[q]);
        }
        for (; j < n; j++) {
            int r = __shfl_sync(gmask, idx, j, 8);
            add8(acc, hv[(size_t)r * 8 + sub]);
        }
        base += n;
    }

    float4 b0 = ((const float4*)bias)[sub * 2];
    float4 b1 = ((const float4*)bias)[sub * 2 + 1];
    float4 v0, v1;
    v0.x = dv * acc[0] + b0.x; v0.y = dv * acc[1] + b0.y;
    v0.z = dv * acc[2] + b0.z; v0.w = dv * acc[3] + b0.w;
    v1.x = dv * acc[4] + b1.x; v1.y = dv * acc[5] + b1.y;
    v1.z = dv * acc[6] + b1.z; v1.w = dv * acc[7] + b1.w;
    float4* op = (float4*)(outp + (size_t)node * NC + sub * 8);
    op[0] = v0; op[1] = v1;
}

// ===================== side stream (static init; no device allocation) =======
struct SideStream {
    cudaStream_t s = nullptr;
    cudaEvent_t evF = nullptr, evJ = nullptr, evF2 = nullptr, evJ2 = nullptr;
    SideStream() {
        if (cudaStreamCreateWithFlags(&s, cudaStreamNonBlocking) != cudaSuccess) s = nullptr;
        if (cudaEventCreateWithFlags(&evF, cudaEventDisableTiming) != cudaSuccess) evF = nullptr;
        if (cudaEventCreateWithFlags(&evJ, cudaEventDisableTiming) != cudaSuccess) evJ = nullptr;
        if (cudaEventCreateWithFlags(&evF2, cudaEventDisableTiming) != cudaSuccess) evF2 = nullptr;
        if (cudaEventCreateWithFlags(&evJ2, cudaEventDisableTiming) != cudaSuccess) evJ2 = nullptr;
    }
};
static SideStream g_ss;

// ===================== launch =================================================
extern "C" void kernel_launch(void* const* d_in, const int* in_sizes, int n_in,
                              void* d_out, int out_size) {
    const float* x  = (const float*)d_in[0];
    const int*   ei = (const int*)d_in[1];
    const float* W1 = (const float*)d_in[2];
    const float* b1 = (const float*)d_in[3];
    const float* W2 = (const float*)d_in[4];
    const float* b2 = (const float*)d_in[5];
    float* out = (float*)d_out;

    const int NB_SCAN = (NN + 1023) / 1024;  // 98
    const int NTILES  = (NN + 127) / 128;    // 782
    const int NB_E4   = (NE / 4 + 255) / 256;

    // agg1 / GEMM2 chunk split at node 50048 (multiple of 128 and of 8)
    const int SPLIT_TILES = 391;                    // rows [0, 50048)
    const int AGG1_BLK_A  = 6256;                   // nodes [0, 50048)
    const int AGG1_BLK_B  = (NN + 7) / 8 - AGG1_BLK_A;  // remaining

    constexpr int SMEM1 = 2 * (128 * 80 + 256 * 80);     // 61440
    constexpr int SMEM2 = 2 * (128 * 80 + 2 * 64 * 80);  // 40960
    cudaFuncSetAttribute(k_gemm_mma<256, HID, 1, 512, 4, 1>,
                         cudaFuncAttributeMaxDynamicSharedMemorySize, SMEM1);
    cudaFuncSetAttribute(k_gemm_mma<64, NC, 2, 256, 2, 2>,
                         cudaFuncAttributeMaxDynamicSharedMemorySize, SMEM2);

    // ---- fork 1: CSR branch on side stream, GEMM1 branch on main stream ----
    bool fork = (g_ss.s && g_ss.evF && g_ss.evJ && g_ss.evF2 && g_ss.evJ2);
    if (fork) fork = (cudaEventRecord(g_ss.evF, 0) == cudaSuccess);
    if (fork) fork = (cudaStreamWaitEvent(g_ss.s, g_ss.evF, 0) == cudaSuccess);
    cudaStream_t cs = fork ? g_ss.s : (cudaStream_t)0;

    // CSR branch (independent of x/W1)
    k_init<<<(NN + 255) / 256, 256, 0, cs>>>();
    k_count<<<NB_E4, 256, 0, cs>>>(ei);
    k_scan1<<<NB_SCAN, 1024, 0, cs>>>();
    k_scan2<<<1, 128, 0, cs>>>(NB_SCAN);
    k_scan3<<<NB_SCAN, 1024, 0, cs>>>();
    k_scatter<<<NB_E4, 256, 0, cs>>>(ei);
    k_prep_w2<<<(HID * NC + 255) / 256, 256, 0, cs>>>(W2);

    // GEMM branch (independent of edges)
    k_prep_w1<<<(DF * HID + 255) / 256, 256>>>(W1);
    k_gemm_mma<256, HID, 1, 512, 4, 1><<<NTILES, 512, SMEM1>>>(x, 0);

    // ---- join 1 ----
    if (fork) {
        bool ok = (cudaEventRecord(g_ss.evJ, g_ss.s) == cudaSuccess);
        if (ok) ok = (cudaStreamWaitEvent(0, g_ss.evJ, 0) == cudaSuccess);
        if (!ok) fork = false;
    }

    // agg1 first chunk: nodes [0, 50048)
    k_agg1_f16<true><<<AGG1_BLK_A, 256>>>(b1, 0);

    if (fork) {
        // fork 2: GEMM2 first half (a1 rows [0,50048)) overlaps agg1 second chunk
        bool ok = (cudaEventRecord(g_ss.evF2, 0) == cudaSuccess);
        if (ok) ok = (cudaStreamWaitEvent(g_ss.s, g_ss.evF2, 0) == cudaSuccess);
        if (ok) {
            k_gemm_mma<64, NC, 2, 256, 2, 2><<<SPLIT_TILES, 256, SMEM2, g_ss.s>>>(nullptr, 0);
            k_agg1_f16<true><<<AGG1_BLK_B, 256>>>(b1, 50048);
            // join 2
            ok = (cudaEventRecord(g_ss.evJ2, g_ss.s) == cudaSuccess);
            if (ok) ok = (cudaStreamWaitEvent(0, g_ss.evJ2, 0) == cudaSuccess);
            (void)ok;
            k_gemm_mma<64, NC, 2, 256, 2, 2><<<NTILES - SPLIT_TILES, 256, SMEM2>>>(nullptr, SPLIT_TILES);
        } else {
            k_agg1_f16<true><<<AGG1_BLK_B, 256>>>(b1, 50048);
            k_gemm_mma<64, NC, 2, 256, 2, 2><<<NTILES, 256, SMEM2>>>(nullptr, 0);
        }
    } else {
        k_agg1_f16<true><<<AGG1_BLK_B, 256>>>(b1, 50048);
        k_gemm_mma<64, NC, 2, 256, 2, 2><<<NTILES, 256, SMEM2>>>(nullptr, 0);
    }

    k_agg2_f16<<<NN / 32, 256>>>(b2, out);
}

// round 15
// speedup vs baseline: 1.0533x; 1.0324x over previous
#include <cuda_runtime.h>
#include <cuda_fp16.h>
#include <cstdint>

#define NN 100000
#define NE 1600000
#define DF 256
#define HID 256
#define NC 64

// ===================== helpers ==============================================
__device__ __forceinline__ uint32_t smem_to_u32(const void* p) {
    uint32_t a;
    asm("{ .reg .u64 t; cvta.to.shared.u64 t, %1; cvt.u32.u64 %0, t; }" : "=r"(a) : "l"(p));
    return a;
}
__device__ __forceinline__ void ldsm4(uint32_t* r, uint32_t addr) {
    asm volatile("ldmatrix.sync.aligned.m8n8.x4.shared.b16 {%0,%1,%2,%3}, [%4];"
                 : "=r"(r[0]), "=r"(r[1]), "=r"(r[2]), "=r"(r[3]) : "r"(addr));
}
__device__ __forceinline__ void mma_f16(float* d, const uint32_t* a, uint32_t b0, uint32_t b1) {
    asm volatile("mma.sync.aligned.m16n8k16.row.col.f32.f16.f16.f32 "
                 "{%0,%1,%2,%3}, {%4,%5,%6,%7}, {%8,%9}, {%0,%1,%2,%3};"
                 : "+f"(d[0]), "+f"(d[1]), "+f"(d[2]), "+f"(d[3])
                 : "r"(a[0]), "r"(a[1]), "r"(a[2]), "r"(a[3]), "r"(b0), "r"(b1));
}
__device__ __forceinline__ uint32_t pack_h2(float x, float y) {
    __half2 h = __floats2half2_rn(x, y);
    return *reinterpret_cast<uint32_t*>(&h);
}
__device__ __forceinline__ void add8s(float* acc, uint4 v, float s) {
    const __half2* hp = reinterpret_cast<const __half2*>(&v);
#pragma unroll
    for (int j = 0; j < 4; j++) {
        float2 f = __half22float2(hp[j]);
        acc[2 * j]     += s * f.x;
        acc[2 * j + 1] += s * f.y;
    }
}
__device__ __forceinline__ void add8(float* acc, uint4 v) {
    const __half2* hp = reinterpret_cast<const __half2*>(&v);
#pragma unroll
    for (int j = 0; j < 4; j++) {
        float2 f = __half22float2(hp[j]);
        acc[2 * j]     += f.x;
        acc[2 * j + 1] += f.y;
    }
}

// ===================== scratch (device globals) ==============================
__device__ __half g_w1t[HID * DF];
__device__ __half g_w2th[NC * HID];
__device__ __half g_w2tl[NC * HID];
__device__ __align__(16) __half g_h1[(size_t)NN * HID];   // UNscaled x@W1
__device__ __align__(16) __half g_a1[(size_t)NN * HID];   // relu(agg1)
__device__ __align__(16) __half g_h2[(size_t)NN * NC];    // dinv-scaled a1@W2
__device__ int   g_deg[NN];
__device__ float g_dinv[NN];
__device__ int   g_offs[NN + 1];
__device__ int   g_cursor[NN];
__device__ int   g_csr[NE];
__device__ int   g_blocksums[128];

// ===================== prep: transposed weights ==============================
__global__ void k_prep_w1(const float* __restrict__ W) {
    int i = blockIdx.x * blockDim.x + threadIdx.x;
    if (i < DF * HID) {
        int k = i / HID, n = i % HID;
        g_w1t[n * DF + k] = __float2half_rn(W[(size_t)k * HID + n]);
    }
}
__global__ void k_prep_w2(const float* __restrict__ W) {
    int i = blockIdx.x * blockDim.x + threadIdx.x;
    if (i < HID * NC) {
        int k = i / NC, n = i % NC;
        float v = W[(size_t)k * NC + n];
        __half h = __float2half_rn(v);
        g_w2th[n * HID + k] = h;
        g_w2tl[n * HID + k] = __float2half_rn(v - __half2float(h));
    }
}

// ===================== CSR build =============================================
__global__ void k_init() {
    int i = blockIdx.x * blockDim.x + threadIdx.x;
    if (i < NN) { g_deg[i] = 1; g_cursor[i] = 0; }
}
__global__ void k_count(const int* __restrict__ ei) {
    int e4 = blockIdx.x * blockDim.x + threadIdx.x;
    if (e4 < NE / 4) {
        int4 c = ((const int4*)(ei + NE))[e4];
        if ((unsigned)c.x < NN) atomicAdd(&g_deg[c.x], 1);
        if ((unsigned)c.y < NN) atomicAdd(&g_deg[c.y], 1);
        if ((unsigned)c.z < NN) atomicAdd(&g_deg[c.z], 1);
        if ((unsigned)c.w < NN) atomicAdd(&g_deg[c.w], 1);
    }
}
__global__ void k_scan1() {   // also emits dinv
    __shared__ int s[1024];
    int tid = threadIdx.x;
    int gid = blockIdx.x * 1024 + tid;
    int v = (gid < NN) ? (g_deg[gid] - 1) : 0;
    if (gid < NN) g_dinv[gid] = rsqrtf((float)(v + 1));
    s[tid] = v;
    __syncthreads();
#pragma unroll
    for (int d = 1; d < 1024; d <<= 1) {
        int t = (tid >= d) ? s[tid - d] : 0;
        __syncthreads();
        s[tid] += t;
        __syncthreads();
    }
    if (gid < NN) g_offs[gid + 1] = s[tid];
    if (tid == 1023) g_blocksums[blockIdx.x] = s[1023];
    if (gid == 0) g_offs[0] = 0;
}
__global__ void k_scan2(int nb) {
    __shared__ int s[128];
    int tid = threadIdx.x;
    int v = (tid < nb) ? g_blocksums[tid] : 0;
    s[tid] = v;
    __syncthreads();
#pragma unroll
    for (int d = 1; d < 128; d <<= 1) {
        int t = (tid >= d) ? s[tid - d] : 0;
        __syncthreads();
        s[tid] += t;
        __syncthreads();
    }
    if (tid < nb) g_blocksums[tid] = s[tid] - v;
}
__global__ void k_scan3() {
    int gid = blockIdx.x * 1024 + threadIdx.x;
    if (gid < NN) g_offs[gid + 1] += g_blocksums[blockIdx.x];
}
__global__ void k_scatter(const int* __restrict__ ei) {
    int e4 = blockIdx.x * blockDim.x + threadIdx.x;
    if (e4 < NE / 4) {
        int4 r = ((const int4*)ei)[e4];
        int4 c = ((const int4*)(ei + NE))[e4];
        if ((unsigned)r.x < NN && (unsigned)c.x < NN)
            g_csr[g_offs[c.x] + atomicAdd(&g_cursor[c.x], 1)] = r.x;
        if ((unsigned)r.y < NN && (unsigned)c.y < NN)
            g_csr[g_offs[c.y] + atomicAdd(&g_cursor[c.y], 1)] = r.y;
        if ((unsigned)r.z < NN && (unsigned)c.z < NN)
            g_csr[g_offs[c.z] + atomicAdd(&g_cursor[c.z], 1)] = r.z;
        if ((unsigned)r.w < NN && (unsigned)c.w < NN)
            g_csr[g_offs[c.w] + atomicAdd(&g_cursor[c.w], 1)] = r.w;
    }
}

// ===================== fp16 HMMA GEMM, 2-stage SMEM pipeline =================
// LAYER 1: C = round16(A_fp32) @ W1(fp16), UNscaled.
// LAYER 2: C = dinv[m] * (A(fp16) @ W2(hi/lo)) — dinv folded in epilogue.
template <int BN, int NT, int LAYER, int THREADS, int WNG, int MINCTA>
__global__ void __launch_bounds__(THREADS, MINCTA) k_gemm_mma(const float* __restrict__ A_ext) {
    constexpr int WTN = BN / WNG;
    constexpr int NTL = WTN / 8;
    constexpr int KDIM = 256;
    constexpr int NCH = KDIM / 32;
    constexpr int ASL = (128 * 4) / THREADS;
    constexpr int BSL = (BN * 4) / THREADS;
    constexpr int A_BYTES = 128 * 80;
    constexpr int B_OFF   = A_BYTES;
    constexpr int B1_OFF  = A_BYTES + BN * 80;
    constexpr int STAGE   = A_BYTES + BN * 80 * ((LAYER == 2) ? 2 : 1);

    extern __shared__ __align__(16) char smem_dyn[];
    const uint32_t smem_b = smem_to_u32(smem_dyn);

    __half* __restrict__ C = (LAYER == 1) ? g_h1 : g_h2;

    const int tid = threadIdx.x, wid = tid >> 5, lane = tid & 31;
    const int bm = blockIdx.x * 128;
    const int m_off = (wid / WNG) * 32;
    const int n_off = (wid % WNG) * WTN;

    float4 pA[ASL][2];
    uint4 pA16[ASL];
    uint4 pB0[BSL], pB1[BSL];

    auto ld_chunk = [&](int c) {
        const int k0 = c * 32;
#pragma unroll
        for (int sl = 0; sl < ASL; sl++) {
            int idx = tid + sl * THREADS;
            int r = idx >> 2, seg = idx & 3;
            int gr = bm + r;
            if (LAYER == 1) {
                if (gr < NN) {
                    const float4* p4 = (const float4*)(A_ext + (size_t)gr * KDIM + k0 + seg * 8);
                    pA[sl][0] = p4[0]; pA[sl][1] = p4[1];
                } else { pA[sl][0] = make_float4(0, 0, 0, 0); pA[sl][1] = pA[sl][0]; }
            } else {
                if (gr < NN)
                    pA16[sl] = *(const uint4*)(g_a1 + (size_t)gr * KDIM + k0 + seg * 8);
                else
                    pA16[sl] = make_uint4(0, 0, 0, 0);
            }
        }
#pragma unroll
        for (int sl = 0; sl < BSL; sl++) {
            int it = tid + sl * THREADS;
            int n = it >> 2, seg = it & 3;
            size_t off = ((size_t)n * KDIM + k0) * 2 + seg * 16;
            if (LAYER == 1) {
                pB0[sl] = *(const uint4*)((const char*)g_w1t + off);
            } else {
                pB0[sl] = *(const uint4*)((const char*)g_w2th + off);
                pB1[sl] = *(const uint4*)((const char*)g_w2tl + off);
            }
        }
    };
    auto st_chunk = [&](int stage) {
        char* sbase = smem_dyn + stage * STAGE;
#pragma unroll
        for (int sl = 0; sl < ASL; sl++) {
            int idx = tid + sl * THREADS;
            int r = idx >> 2, seg = idx & 3;
            if (LAYER == 1) {
                uint4 h4;
                h4.x = pack_h2(pA[sl][0].x, pA[sl][0].y);
                h4.y = pack_h2(pA[sl][0].z, pA[sl][0].w);
                h4.z = pack_h2(pA[sl][1].x, pA[sl][1].y);
                h4.w = pack_h2(pA[sl][1].z, pA[sl][1].w);
                *(uint4*)(sbase + r * 80 + seg * 16) = h4;
            } else {
                *(uint4*)(sbase + r * 80 + seg * 16) = pA16[sl];
            }
        }
#pragma unroll
        for (int sl = 0; sl < BSL; sl++) {
            int it = tid + sl * THREADS;
            int n = it >> 2, seg = it & 3;
            *(uint4*)(sbase + B_OFF + n * 80 + seg * 16) = pB0[sl];
            if (LAYER == 2)
                *(uint4*)(sbase + B1_OFF + n * 80 + seg * 16) = pB1[sl];
        }
    };

    float acc[2][NTL][4];
#pragma unroll
    for (int t = 0; t < 2; t++)
#pragma unroll
        for (int p = 0; p < NTL; p++)
#pragma unroll
            for (int j = 0; j < 4; j++) acc[t][p][j] = 0.f;

    ld_chunk(0);
    st_chunk(0);
    __syncthreads();

    for (int c = 0; c < NCH; c++) {
        const int stg = c & 1;
        if (c + 1 < NCH) ld_chunk(c + 1);

        const uint32_t a_st = smem_b + stg * STAGE;
        const uint32_t b0_st = a_st + B_OFF;
        const uint32_t b1_st = a_st + B1_OFF;

#pragma unroll
        for (int s = 0; s < 2; s++) {
            const int kb = s * 32;
            uint32_t a0[2][4];
#pragma unroll
            for (int t = 0; t < 2; t++) {
                uint32_t ra = (uint32_t)(m_off + t * 16 + (lane & 15)) * 80 + kb + (lane >> 4) * 16;
                ldsm4(a0[t], a_st + ra);
            }
#pragma unroll
            for (int p = 0; p < NTL / 2; p++) {
                uint32_t rb = (uint32_t)(n_off + p * 16 + (lane >> 4) * 8 + (lane & 7)) * 80 +
                              kb + ((lane >> 3) & 1) * 16;
                uint32_t b0[4];
                ldsm4(b0, b0_st + rb);
#pragma unroll
                for (int t = 0; t < 2; t++) {
                    mma_f16(acc[t][2 * p],     a0[t], b0[0], b0[1]);
                    mma_f16(acc[t][2 * p + 1], a0[t], b0[2], b0[3]);
                }
                if (LAYER == 2) {
                    uint32_t b1[4];
                    ldsm4(b1, b1_st + rb);
#pragma unroll
                    for (int t = 0; t < 2; t++) {
                        mma_f16(acc[t][2 * p],     a0[t], b1[0], b1[1]);
                        mma_f16(acc[t][2 * p + 1], a0[t], b1[2], b1[3]);
                    }
                }
            }
        }

        if (c + 1 < NCH) {
            st_chunk((c + 1) & 1);
            __syncthreads();
        }
    }

#pragma unroll
    for (int t = 0; t < 2; t++) {
        int m0 = bm + m_off + t * 16 + (lane >> 2);
        int m1 = m0 + 8;
        float s0 = 1.f, s1 = 1.f;
        if (LAYER == 2) {
            s0 = (m0 < NN) ? g_dinv[m0] : 0.f;
            s1 = (m1 < NN) ? g_dinv[m1] : 0.f;
        }
#pragma unroll
        for (int p = 0; p < NTL; p++) {
            int n = n_off + p * 8 + (lane & 3) * 2;
            if (m0 < NN)
                *(__half2*)(C + (size_t)m0 * NT + n) =
                    __floats2half2_rn(s0 * acc[t][p][0], s0 * acc[t][p][1]);
            if (m1 < NN)
                *(__half2*)(C + (size_t)m1 * NT + n) =
                    __floats2half2_rn(s1 * acc[t][p][2], s1 * acc[t][p][3]);
        }
    }
}

// ===================== aggregation ===========================================
// Layer 1 (R12 form): one warp per node, 8 nodes per block, single launch.
template <bool RELU>
__global__ void __launch_bounds__(256) k_agg1_f16(const float* __restrict__ bias) {
    const uint4* __restrict__ hv = (const uint4*)g_h1;
    uint4* __restrict__ ov = (uint4*)g_a1;

    const int tid = threadIdx.x, wid = tid >> 5, lane = tid & 31;
    const int node = blockIdx.x * 8 + wid;
    const int s = g_offs[node], e = g_offs[node + 1];
    const float dv = g_dinv[node];

    float acc[8];
    {
        uint4 v = hv[(size_t)node * 32 + lane];
        const __half2* hp = reinterpret_cast<const __half2*>(&v);
#pragma unroll
        for (int j = 0; j < 4; j++) {
            float2 f = __half22float2(hp[j]);
            acc[2 * j] = dv * f.x; acc[2 * j + 1] = dv * f.y;
        }
    }

    int base = s;
    while (base < e) {
        int n = e - base;
        if (n > 32) n = 32;
        int idx = g_csr[base + min(lane, n - 1)];
        int j = 0;
        for (; j + 8 <= n; j += 8) {
            int r[8]; float d[8]; uint4 t[8];
#pragma unroll
            for (int q = 0; q < 8; q++) r[q] = __shfl_sync(0xFFFFFFFFu, idx, j + q);
#pragma unroll
            for (int q = 0; q < 8; q++) d[q] = g_dinv[r[q]];
#pragma unroll
            for (int q = 0; q < 8; q++) t[q] = hv[(size_t)r[q] * 32 + lane];
#pragma unroll
            for (int q = 0; q < 8; q++) add8s(acc, t[q], d[q]);
        }
        for (; j < n; j++) {
            int r = __shfl_sync(0xFFFFFFFFu, idx, j);
            add8s(acc, hv[(size_t)r * 32 + lane], g_dinv[r]);
        }
        base += n;
    }

    float4 b0 = ((const float4*)bias)[lane * 2];
    float4 b1 = ((const float4*)bias)[lane * 2 + 1];
    float o[8];
    o[0] = dv * acc[0] + b0.x; o[1] = dv * acc[1] + b0.y;
    o[2] = dv * acc[2] + b0.z; o[3] = dv * acc[3] + b0.w;
    o[4] = dv * acc[4] + b1.x; o[5] = dv * acc[5] + b1.y;
    o[6] = dv * acc[6] + b1.z; o[7] = dv * acc[7] + b1.w;
    if (RELU) {
#pragma unroll
        for (int j = 0; j < 8; j++) o[j] = fmaxf(o[j], 0.f);
    }
    uint4 pk;
    __half2* op = reinterpret_cast<__half2*>(&pk);
#pragma unroll
    for (int j = 0; j < 4; j++) op[j] = __floats2half2_rn(o[2 * j], o[2 * j + 1]);
    ov[(size_t)node * 32 + lane] = pk;
}

// Layer 2: h2 PRE-scaled by dinv[m] (GEMM2 epilogue) -> plain adds. 8 thr/node,
// single launch (R12 layout).
__global__ void __launch_bounds__(256) k_agg2_f16(const float* __restrict__ bias,
                                                  float* __restrict__ outp) {
    const uint4* __restrict__ hv = (const uint4*)g_h2;

    const int tid = threadIdx.x;
    const int sub = tid & 7;
    const int node = blockIdx.x * 32 + (tid >> 3);
    const int lane = tid & 31;
    const unsigned gmask = 0xFFu << (lane & ~7);

    const int s = g_offs[node], e = g_offs[node + 1];
    const float dv = g_dinv[node];

    float acc[8];
    {
        uint4 v = hv[(size_t)node * 8 + sub];   // already dinv[v]-scaled
        const __half2* hp = reinterpret_cast<const __half2*>(&v);
#pragma unroll
        for (int j = 0; j < 4; j++) {
            float2 f = __half22float2(hp[j]);
            acc[2 * j] = f.x; acc[2 * j + 1] = f.y;
        }
    }

    int base = s;
    while (base < e) {
        int n = e - base;
        if (n > 8) n = 8;
        int idx = g_csr[base + min(sub, n - 1)];
        int j = 0;
        for (; j + 8 <= n; j += 8) {
            int r[8]; uint4 t[8];
#pragma unroll
            for (int q = 0; q < 8; q++) r[q] = __shfl_sync(gmask, idx, j + q, 8);
#pragma unroll
            for (int q = 0; q < 8; q++) t[q] = hv[(size_t)r[q] * 8 + sub];
#pragma unroll
            for (int q = 0; q < 8; q++) add8(acc, t[q]);
        }
        for (; j < n; j++) {
            int r = __shfl_sync(gmask, idx, j, 8);
            add8(acc, hv[(size_t)r * 8 + sub]);
        }
        base += n;
    }

    float4 b0 = ((const float4*)bias)[sub * 2];
    float4 b1 = ((const float4*)bias)[sub * 2 + 1];
    float4 v0, v1;
    v0.x = dv * acc[0] + b0.x; v0.y = dv * acc[1] + b0.y;
    v0.z = dv * acc[2] + b0.z; v0.w = dv * acc[3] + b0.w;
    v1.x = dv * acc[4] + b1.x; v1.y = dv * acc[5] + b1.y;
    v1.z = dv * acc[6] + b1.z; v1.w = dv * acc[7] + b1.w;
    float4* op = (float4*)(outp + (size_t)node * NC + sub * 8);
    op[0] = v0; op[1] = v1;
}

// ===================== side stream (static init; no device allocation) =======
struct SideStream {
    cudaStream_t s = nullptr;
    cudaEvent_t evF = nullptr, evJ = nullptr;
    SideStream() {
        if (cudaStreamCreateWithFlags(&s, cudaStreamNonBlocking) != cudaSuccess) s = nullptr;
        if (cudaEventCreateWithFlags(&evF, cudaEventDisableTiming) != cudaSuccess) evF = nullptr;
        if (cudaEventCreateWithFlags(&evJ, cudaEventDisableTiming) != cudaSuccess) evJ = nullptr;
    }
};
static SideStream g_ss;

// ===================== launch =================================================
extern "C" void kernel_launch(void* const* d_in, const int* in_sizes, int n_in,
                              void* d_out, int out_size) {
    const float* x  = (const float*)d_in[0];
    const int*   ei = (const int*)d_in[1];
    const float* W1 = (const float*)d_in[2];
    const float* b1 = (const float*)d_in[3];
    const float* W2 = (const float*)d_in[4];
    const float* b2 = (const float*)d_in[5];
    float* out = (float*)d_out;

    const int NB_SCAN = (NN + 1023) / 1024;  // 98
    const int NTILES  = (NN + 127) / 128;    // 782
    const int NB_E4   = (NE / 4 + 255) / 256;

    constexpr int SMEM1 = 2 * (128 * 80 + 256 * 80);     // 61440
    constexpr int SMEM2 = 2 * (128 * 80 + 2 * 64 * 80);  // 40960
    cudaFuncSetAttribute(k_gemm_mma<256, HID, 1, 512, 4, 1>,
                         cudaFuncAttributeMaxDynamicSharedMemorySize, SMEM1);
    cudaFuncSetAttribute(k_gemm_mma<64, NC, 2, 256, 2, 2>,
                         cudaFuncAttributeMaxDynamicSharedMemorySize, SMEM2);

    // ---- fork: CSR branch on side stream, GEMM1 branch on main stream ----
    bool fork = (g_ss.s && g_ss.evF && g_ss.evJ);
    if (fork) fork = (cudaEventRecord(g_ss.evF, 0) == cudaSuccess);
    if (fork) fork = (cudaStreamWaitEvent(g_ss.s, g_ss.evF, 0) == cudaSuccess);
    cudaStream_t cs = fork ? g_ss.s : (cudaStream_t)0;

    // CSR branch (independent of x/W1)
    k_init<<<(NN + 255) / 256, 256, 0, cs>>>();
    k_count<<<NB_E4, 256, 0, cs>>>(ei);
    k_scan1<<<NB_SCAN, 1024, 0, cs>>>();
    k_scan2<<<1, 128, 0, cs>>>(NB_SCAN);
    k_scan3<<<NB_SCAN, 1024, 0, cs>>>();
    k_scatter<<<NB_E4, 256, 0, cs>>>(ei);
    k_prep_w2<<<(HID * NC + 255) / 256, 256, 0, cs>>>(W2);

    // GEMM branch (independent of edges)
    k_prep_w1<<<(DF * HID + 255) / 256, 256>>>(W1);
    k_gemm_mma<256, HID, 1, 512, 4, 1><<<NTILES, 512, SMEM1>>>(x);

    // ---- join ----
    if (fork) {
        bool ok = (cudaEventRecord(g_ss.evJ, g_ss.s) == cudaSuccess);
        if (ok) ok = (cudaStreamWaitEvent(0, g_ss.evJ, 0) == cudaSuccess);
        (void)ok;
    }

    // fused remainder (needs both branches) — R12 schedule, single launches
    k_agg1_f16<true><<<NN / 8, 256>>>(b1);
    k_gemm_mma<64, NC, 2, 256, 2, 2><<<NTILES, 256, SMEM2>>>(nullptr);
    k_agg2_f16<<<NN / 32, 256>>>(b2, out);
}